// round 14
// baseline (speedup 1.0000x reference)
#include <cuda_runtime.h>
#include <math.h>
#include <stdint.h>

// ---------------- problem constants ----------------
#define NB      2
#define TSEQ    2048
#define NDIM    2048
#define NH      16
#define NQLR    1536
#define NKVLR   512
#define NRD     64
#define NND     128
#define NVD     128
#define NTOK    (NB * TSEQ)        // 4096
#define DQK     (NND + NRD)        // 192
#define KVP     640                 // padded kv_down output width (576 -> 640)
#define EPSV    1e-6f

// ---------------- scratch (no allocations allowed) ----------------
__device__ float g_cq     [(size_t)NTOK * NQLR];
__device__ float g_qn     [(size_t)NTOK * NH * NND];
__device__ float g_qr     [(size_t)NTOK * NH * NRD];
__device__ float g_q      [(size_t)NTOK * NH * DQK];
__device__ float g_kvraw  [(size_t)NTOK * KVP];
__device__ float g_ckv    [(size_t)NTOK * NKVLR];
__device__ float g_kr     [(size_t)NTOK * NRD];
__device__ float g_kv     [(size_t)NTOK * NH * (NND + NVD)];
__device__ float g_k      [(size_t)NTOK * NH * DQK];
__device__ float g_ao     [(size_t)NTOK * NH * NVD];
__device__ float g_kdwpad [(size_t)NDIM * KVP];

// ---------------- helpers ----------------
__device__ __forceinline__ float warp_sum(float v) {
#pragma unroll
    for (int o = 16; o; o >>= 1) v += __shfl_xor_sync(0xffffffffu, v, o);
    return v;
}

__device__ __forceinline__ uint32_t f2tf32(float f) {
    uint32_t r;
    asm("cvt.rna.tf32.f32 %0, %1;" : "=r"(r) : "f"(f));
    return r;
}

__device__ __forceinline__ void mma_tf32(
    float& c0, float& c1, float& c2, float& c3,
    uint32_t a0, uint32_t a1, uint32_t a2, uint32_t a3,
    uint32_t b0, uint32_t b1)
{
    asm volatile(
        "mma.sync.aligned.m16n8k8.row.col.f32.tf32.tf32.f32 "
        "{%0,%1,%2,%3}, {%4,%5,%6,%7}, {%8,%9}, {%0,%1,%2,%3};"
        : "+f"(c0), "+f"(c1), "+f"(c2), "+f"(c3)
        : "r"(a0), "r"(a1), "r"(a2), "r"(a3), "r"(b0), "r"(b1));
}

__device__ __forceinline__ void cp16(uint32_t dst_smem, const void* src) {
    asm volatile("cp.async.cg.shared.global [%0], [%1], 16;\n"
                 :: "r"(dst_smem), "l"(src) : "memory");
}
#define CP_COMMIT() asm volatile("cp.async.commit_group;\n" ::: "memory")
#define CP_WAIT(N)  asm volatile("cp.async.wait_group %0;\n" :: "n"(N) : "memory")

// ============ tf32 tensor-core GEMM v2: 3-stage cp.async pipeline ============
// 128x128x32 block tile, 8 warps, 64x32 warp tile. Raw fp32 staged in smem,
// tf32 conversion in the fragment load. C = A @ B row-major.
// M%128==0, N%128==0, K%32==0, K>=64.
#define AS_W 4608                 // 128*36 floats
#define BS_W 4352                 // 32*136 floats
#define STG_W (AS_W + BS_W)       // 8960
#define GEMM_SMEM_BYTES (3 * STG_W * 4)   // 107520

__device__ __forceinline__ void gemm_issue_stage(
    const float* __restrict__ A, const float* __restrict__ B,
    uint32_t sdst, int m0, int n0, int k0, int K, int N, int tid)
{
    // A tile: 128 rows x 8 quads
#pragma unroll
    for (int p = 0; p < 4; p++) {
        int qa = p * 256 + tid;
        int row = qa >> 3, qk = (qa & 7) << 2;
        cp16(sdst + (row * 36 + qk) * 4,
             A + (size_t)(m0 + row) * K + k0 + qk);
    }
    // B tile: 32 rows x 32 quads
#pragma unroll
    for (int p = 0; p < 4; p++) {
        int qb = p * 256 + tid;
        int row = qb >> 5, qn = (qb & 31) << 2;
        cp16(sdst + (AS_W + row * 136 + qn) * 4,
             B + (size_t)(k0 + row) * N + n0 + qn);
    }
}

__global__ __launch_bounds__(256, 1) void gemm_tf32(
    const float* __restrict__ A, const float* __restrict__ B,
    float* __restrict__ C, int M, int N, int K)
{
    extern __shared__ float gsm[];
    const uint32_t smb = (uint32_t)__cvta_generic_to_shared(gsm);

    const int tid  = threadIdx.x;
    const int wid  = tid >> 5;
    const int lane = tid & 31;
    const int g    = lane >> 2;
    const int tg   = lane & 3;
    const int warp_m = (wid >> 2) * 64;
    const int warp_n = (wid & 3) * 32;

    const int m0 = blockIdx.y << 7;
    const int n0 = blockIdx.x << 7;

    float acc[4][4][4];
#pragma unroll
    for (int mt = 0; mt < 4; mt++)
#pragma unroll
        for (int nt = 0; nt < 4; nt++)
#pragma unroll
            for (int c = 0; c < 4; c++) acc[mt][nt][c] = 0.f;

    const int nk = K >> 5;

    // prologue: stages 0 and 1 in flight
    gemm_issue_stage(A, B, smb + 0 * STG_W * 4, m0, n0, 0, K, N, tid);
    CP_COMMIT();
    gemm_issue_stage(A, B, smb + 1 * STG_W * 4, m0, n0, 32, K, N, tid);
    CP_COMMIT();

    for (int it = 0; it < nk; it++) {
        if (it == nk - 1) { CP_WAIT(0); } else { CP_WAIT(1); }
        __syncthreads();

        if (it + 2 < nk) {
            gemm_issue_stage(A, B, smb + ((it + 2) % 3) * STG_W * 4,
                             m0, n0, (it + 2) << 5, K, N, tid);
            CP_COMMIT();
        }

        const float* As = gsm + (it % 3) * STG_W;
        const float* Bs = As + AS_W;

#pragma unroll
        for (int k8 = 0; k8 < 4; k8++) {
            const int kk = k8 * 8;
            uint32_t afr[4][4], bfr[4][2];
#pragma unroll
            for (int mt = 0; mt < 4; mt++) {
                const int m = warp_m + mt * 16;
                afr[mt][0] = f2tf32(As[(m + g) * 36 + kk + tg]);
                afr[mt][1] = f2tf32(As[(m + g + 8) * 36 + kk + tg]);
                afr[mt][2] = f2tf32(As[(m + g) * 36 + kk + tg + 4]);
                afr[mt][3] = f2tf32(As[(m + g + 8) * 36 + kk + tg + 4]);
            }
#pragma unroll
            for (int nt = 0; nt < 4; nt++) {
                const int n = warp_n + nt * 8;
                bfr[nt][0] = f2tf32(Bs[(kk + tg) * 136 + n + g]);
                bfr[nt][1] = f2tf32(Bs[(kk + tg + 4) * 136 + n + g]);
            }
#pragma unroll
            for (int mt = 0; mt < 4; mt++)
#pragma unroll
                for (int nt = 0; nt < 4; nt++)
                    mma_tf32(acc[mt][nt][0], acc[mt][nt][1], acc[mt][nt][2], acc[mt][nt][3],
                             afr[mt][0], afr[mt][1], afr[mt][2], afr[mt][3],
                             bfr[nt][0], bfr[nt][1]);
        }
        __syncthreads();   // stage consumed; safe for reuse by it+2 prefetch next iter
    }

#pragma unroll
    for (int mt = 0; mt < 4; mt++) {
        const int row = m0 + warp_m + mt * 16 + g;
#pragma unroll
        for (int nt = 0; nt < 4; nt++) {
            const int col = n0 + warp_n + nt * 8 + tg * 2;
            *(float2*)(C + (size_t)row * N + col)       = make_float2(acc[mt][nt][0], acc[mt][nt][1]);
            *(float2*)(C + (size_t)(row + 8) * N + col) = make_float2(acc[mt][nt][2], acc[mt][nt][3]);
        }
    }
}

// ---------------- pad kv_down_w (2048x576) into (2048x640), zero-filled ----------------
__global__ __launch_bounds__(256) void pad_kdw(
    const float* __restrict__ w, float* __restrict__ o)
{
    int idx = blockIdx.x * 256 + threadIdx.x;
    int r = idx / KVP, c = idx - r * KVP;
    o[idx] = (c < NKVLR + NRD) ? w[r * (NKVLR + NRD) + c] : 0.f;
}

// ---------------- row-wise rmsnorm (in place), 256 threads ----------------
__global__ __launch_bounds__(256) void rmsnorm_rows(
    float* __restrict__ x, const float* __restrict__ w, int len)
{
    __shared__ float sb[8];
    float* row = x + (size_t)blockIdx.x * len;
    float ss = 0.f;
    for (int i = threadIdx.x; i < len; i += 256) { float v = row[i]; ss += v * v; }
    ss = warp_sum(ss);
    if ((threadIdx.x & 31) == 0) sb[threadIdx.x >> 5] = ss;
    __syncthreads();
    float tot = 0.f;
#pragma unroll
    for (int i = 0; i < 8; i++) tot += sb[i];
    float sc = rsqrtf(tot / (float)len + EPSV);
    for (int i = threadIdx.x; i < len; i += 256) row[i] = row[i] * sc * w[i];
}

// ---------------- build q ----------------
__global__ __launch_bounds__(128) void q_build(
    const float* __restrict__ qn, const float* __restrict__ qr,
    const float* __restrict__ qhw,
    const float* __restrict__ fc, const float* __restrict__ fs,
    float* __restrict__ q)
{
    __shared__ float sb[4];
    const int token = blockIdx.y, h = blockIdx.x;
    const int t = token & (TSEQ - 1);
    const float* xn = qn + (size_t)token * NH * NND + h * NND;
    float v = xn[threadIdx.x];
    float ss = warp_sum(v * v);
    if ((threadIdx.x & 31) == 0) sb[threadIdx.x >> 5] = ss;
    __syncthreads();
    float tot = sb[0] + sb[1] + sb[2] + sb[3];
    float sc = rsqrtf(tot / (float)NND + EPSV);
    float* qo = q + ((size_t)token * NH + h) * DQK;
    qo[threadIdx.x] = v * sc * qhw[threadIdx.x];
    if (threadIdx.x < NRD / 2) {
        int i = threadIdx.x;
        const float* xr = qr + (size_t)token * NH * NRD + h * NRD;
        float a = xr[2 * i], b = xr[2 * i + 1];
        float c = fc[t * (NRD / 2) + i], s = fs[t * (NRD / 2) + i];
        qo[NND + 2 * i]     = a * c - b * s;
        qo[NND + 2 * i + 1] = a * s + b * c;
    }
}

// ---------------- kv post (reads padded kvraw, stride KVP) ----------------
__global__ __launch_bounds__(128) void kv_post(
    const float* __restrict__ kvraw, const float* __restrict__ kvw,
    const float* __restrict__ fc, const float* __restrict__ fs,
    float* __restrict__ ckv, float* __restrict__ kr)
{
    __shared__ float sb[4];
    const int token = blockIdx.x;
    const int t = token & (TSEQ - 1);
    const float* row = kvraw + (size_t)token * KVP;
    float ss = 0.f;
    for (int i = threadIdx.x; i < NKVLR; i += 128) { float v = row[i]; ss += v * v; }
    ss = warp_sum(ss);
    if ((threadIdx.x & 31) == 0) sb[threadIdx.x >> 5] = ss;
    __syncthreads();
    float tot = sb[0] + sb[1] + sb[2] + sb[3];
    float sc = rsqrtf(tot / (float)NKVLR + EPSV);
    for (int i = threadIdx.x; i < NKVLR; i += 128)
        ckv[(size_t)token * NKVLR + i] = row[i] * sc * kvw[i];
    if (threadIdx.x < NRD / 2) {
        int i = threadIdx.x;
        float a = row[NKVLR + 2 * i], b = row[NKVLR + 2 * i + 1];
        float c = fc[t * (NRD / 2) + i], s = fs[t * (NRD / 2) + i];
        kr[(size_t)token * NRD + 2 * i]     = a * c - b * s;
        kr[(size_t)token * NRD + 2 * i + 1] = a * s + b * c;
    }
}

// ---------------- build k ----------------
__global__ __launch_bounds__(128) void k_build(
    const float* __restrict__ kv, const float* __restrict__ khw,
    const float* __restrict__ kr, float* __restrict__ k)
{
    __shared__ float sb[4];
    const int token = blockIdx.y, h = blockIdx.x;
    const float* kn = kv + ((size_t)token * NH + h) * (NND + NVD);
    float v = kn[threadIdx.x];
    float ss = warp_sum(v * v);
    if ((threadIdx.x & 31) == 0) sb[threadIdx.x >> 5] = ss;
    __syncthreads();
    float tot = sb[0] + sb[1] + sb[2] + sb[3];
    float sc = rsqrtf(tot / (float)NND + EPSV);
    float* ko = k + ((size_t)token * NH + h) * DQK;
    ko[threadIdx.x] = v * sc * khw[threadIdx.x];
    if (threadIdx.x < NRD) ko[NND + threadIdx.x] = kr[(size_t)token * NRD + threadIdx.x];
}

// ============ causal flash attention v5: tf32 MMA for QK^T and PV ============
#define QS_OFF 0
#define KS_OFF 12544
#define KS_SZ  12544
#define VS_OFF 37632
#define PS_OFF 46336
#define MX_OFF 50688
#define SX_OFF 50816
#define ATTN_SMEM_BYTES (50944 * 4)   // 203776

__global__ __launch_bounds__(256) void attn_kernel(
    const float* __restrict__ q, const float* __restrict__ k,
    const float* __restrict__ kv, float* __restrict__ ao)
{
    extern __shared__ float sm[];
    float* Qs = sm + QS_OFF;
    float* Vs = sm + VS_OFF;
    float* Ps = sm + PS_OFF;
    float* Mx = sm + MX_OFF;
    float* Sx = sm + SX_OFF;
    const uint32_t smb = (uint32_t)__cvta_generic_to_shared(sm);

    const int tid  = threadIdx.x;
    const int wid  = tid >> 5;
    const int lane = tid & 31;
    const int g    = lane >> 2;
    const int tg   = lane & 3;
    const int warp_m = (wid >> 1) * 16;
    const int half   = wid & 1;
    const int row0 = warp_m + g;
    const int row1 = row0 + 8;

    const int qt = (int)gridDim.x - 1 - (int)blockIdx.x;
    const int bh = blockIdx.y;
    const int b = bh >> 4, h = bh & 15;
    const int qt0 = qt << 6;
    const int bT = b * TSEQ;
    const float SCALE = 0.07216878364870322f;

    const float* qh = q  + ((size_t)(bT + qt0) * NH + h) * DQK;
    const float* vh = kv + ((size_t)bT * NH + h) * (NND + NVD) + NND;

    const int lrow = tid >> 2;
    const int lq0  = (tid & 3) * 12;

#pragma unroll
    for (int p = 0; p < 12; p++) {
        int quad = lq0 + p;
        cp16(smb + (QS_OFF + lrow * 196 + quad * 4) * 4,
             qh + (size_t)lrow * (NH * DQK) + quad * 4);
    }
    {
        const float* kh0 = k + ((size_t)bT * NH + h) * DQK;
#pragma unroll
        for (int p = 0; p < 12; p++) {
            int quad = lq0 + p;
            cp16(smb + (KS_OFF + lrow * 196 + quad * 4) * 4,
                 kh0 + (size_t)lrow * (NH * DQK) + quad * 4);
        }
    }
    CP_COMMIT();
#pragma unroll
    for (int p = 0; p < 8; p++) {
        int c = p * 256 + tid;
        int j = c >> 5, off = (c & 31) * 4;
        cp16(smb + (VS_OFF + j * 136 + off) * 4,
             vh + (size_t)j * (NH * (NND + NVD)) + off);
    }
    CP_COMMIT();

    float rm0 = -1e30f, rm1 = -1e30f, rl0 = 0.f, rl1 = 0.f;
    float acc[8][4];
#pragma unroll
    for (int nt = 0; nt < 8; nt++)
#pragma unroll
        for (int c = 0; c < 4; c++) acc[nt][c] = 0.f;

    for (int kt = 0; kt <= qt; kt++) {
        CP_WAIT(1);
        __syncthreads();

        if (kt == 0) {
            for (int i = tid; i < 12544; i += 256)
                Qs[i] = __uint_as_float(f2tf32(Qs[i]));
            __syncthreads();
        }

        if (kt < qt) {
            const float* khn = k + ((size_t)(bT + (kt + 1) * 64) * NH + h) * DQK;
            const uint32_t kdst = smb + (KS_OFF + ((kt + 1) & 1) * KS_SZ) * 4;
#pragma unroll
            for (int p = 0; p < 12; p++) {
                int quad = lq0 + p;
                cp16(kdst + (lrow * 196 + quad * 4) * 4,
                     khn + (size_t)lrow * (NH * DQK) + quad * 4);
            }
            CP_COMMIT();
        }

        const float* Ks = sm + KS_OFF + (kt & 1) * KS_SZ;
        const int warp_n = half * 32;

        float s[4][4];
#pragma unroll
        for (int nt = 0; nt < 4; nt++)
#pragma unroll
            for (int c = 0; c < 4; c++) s[nt][c] = 0.f;

#pragma unroll 4
        for (int ks = 0; ks < 24; ks++) {
            const int kk = ks * 8;
            uint32_t a0 = __float_as_uint(Qs[row0 * 196 + kk + tg]);
            uint32_t a1 = __float_as_uint(Qs[row1 * 196 + kk + tg]);
            uint32_t a2 = __float_as_uint(Qs[row0 * 196 + kk + tg + 4]);
            uint32_t a3 = __float_as_uint(Qs[row1 * 196 + kk + tg + 4]);
#pragma unroll
            for (int nt = 0; nt < 4; nt++) {
                const int n = warp_n + nt * 8 + g;
                uint32_t b0 = f2tf32(Ks[n * 196 + kk + tg]);
                uint32_t b1 = f2tf32(Ks[n * 196 + kk + tg + 4]);
                mma_tf32(s[nt][0], s[nt][1], s[nt][2], s[nt][3],
                         a0, a1, a2, a3, b0, b1);
            }
        }

#pragma unroll
        for (int nt = 0; nt < 4; nt++)
#pragma unroll
            for (int c = 0; c < 4; c++) s[nt][c] *= SCALE;
        if (kt == qt) {
#pragma unroll
            for (int nt = 0; nt < 4; nt++) {
                int col = warp_n + nt * 8 + 2 * tg;
                if (col     > row0) s[nt][0] = -1e30f;
                if (col + 1 > row0) s[nt][1] = -1e30f;
                if (col     > row1) s[nt][2] = -1e30f;
                if (col + 1 > row1) s[nt][3] = -1e30f;
            }
        }

        float m0p = -1e30f, m1p = -1e30f;
#pragma unroll
        for (int nt = 0; nt < 4; nt++) {
            m0p = fmaxf(m0p, fmaxf(s[nt][0], s[nt][1]));
            m1p = fmaxf(m1p, fmaxf(s[nt][2], s[nt][3]));
        }
        m0p = fmaxf(m0p, __shfl_xor_sync(0xffffffffu, m0p, 1));
        m0p = fmaxf(m0p, __shfl_xor_sync(0xffffffffu, m0p, 2));
        m1p = fmaxf(m1p, __shfl_xor_sync(0xffffffffu, m1p, 1));
        m1p = fmaxf(m1p, __shfl_xor_sync(0xffffffffu, m1p, 2));
        if (tg == 0) {
            Mx[half * 64 + row0] = m0p;
            Mx[half * 64 + row1] = m1p;
        }
        __syncthreads();

        float mn0 = fmaxf(rm0, fmaxf(Mx[row0], Mx[64 + row0]));
        float mn1 = fmaxf(rm1, fmaxf(Mx[row1], Mx[64 + row1]));
        float corr0 = __expf(rm0 - mn0);
        float corr1 = __expf(rm1 - mn1);
        rm0 = mn0; rm1 = mn1;

        float s0p = 0.f, s1p = 0.f;
#pragma unroll
        for (int nt = 0; nt < 4; nt++) {
            float e0 = __expf(s[nt][0] - mn0);
            float e1 = __expf(s[nt][1] - mn0);
            float e2 = __expf(s[nt][2] - mn1);
            float e3 = __expf(s[nt][3] - mn1);
            s0p += e0 + e1;
            s1p += e2 + e3;
            int col = warp_n + nt * 8 + 2 * tg;
            *(float2*)&Ps[row0 * 68 + col] =
                make_float2(__uint_as_float(f2tf32(e0)), __uint_as_float(f2tf32(e1)));
            *(float2*)&Ps[row1 * 68 + col] =
                make_float2(__uint_as_float(f2tf32(e2)), __uint_as_float(f2tf32(e3)));
        }
        s0p += __shfl_xor_sync(0xffffffffu, s0p, 1);
        s0p += __shfl_xor_sync(0xffffffffu, s0p, 2);
        s1p += __shfl_xor_sync(0xffffffffu, s1p, 1);
        s1p += __shfl_xor_sync(0xffffffffu, s1p, 2);
        if (tg == 0) {
            Sx[half * 64 + row0] = s0p;
            Sx[half * 64 + row1] = s1p;
        }

#pragma unroll
        for (int nt = 0; nt < 8; nt++) {
            acc[nt][0] *= corr0; acc[nt][1] *= corr0;
            acc[nt][2] *= corr1; acc[nt][3] *= corr1;
        }

        if (kt < qt) { CP_WAIT(1); } else { CP_WAIT(0); }
        __syncthreads();

        rl0 = rl0 * corr0 + Sx[row0] + Sx[64 + row0];
        rl1 = rl1 * corr1 + Sx[row1] + Sx[64 + row1];

#pragma unroll
        for (int ks = 0; ks < 8; ks++) {
            const int kk = ks * 8;
            uint32_t a0 = __float_as_uint(Ps[row0 * 68 + kk + tg]);
            uint32_t a1 = __float_as_uint(Ps[row1 * 68 + kk + tg]);
            uint32_t a2 = __float_as_uint(Ps[row0 * 68 + kk + tg + 4]);
            uint32_t a3 = __float_as_uint(Ps[row1 * 68 + kk + tg + 4]);
#pragma unroll
            for (int nt = 0; nt < 8; nt++) {
                const int n = half * 64 + nt * 8 + g;
                uint32_t b0 = f2tf32(Vs[(kk + tg) * 136 + n]);
                uint32_t b1 = f2tf32(Vs[(kk + tg + 4) * 136 + n]);
                mma_tf32(acc[nt][0], acc[nt][1], acc[nt][2], acc[nt][3],
                         a0, a1, a2, a3, b0, b1);
            }
        }
        __syncthreads();

        if (kt < qt) {
            const float* vhn = vh + (size_t)(kt + 1) * 64 * (NH * (NND + NVD));
#pragma unroll
            for (int p = 0; p < 8; p++) {
                int c = p * 256 + tid;
                int j = c >> 5, off = (c & 31) * 4;
                cp16(smb + (VS_OFF + j * 136 + off) * 4,
                     vhn + (size_t)j * (NH * (NND + NVD)) + off);
            }
            CP_COMMIT();
        }
    }

    const float inv0 = 1.f / rl0;
    const float inv1 = 1.f / rl1;
    float* op0 = ao + ((size_t)(bT + qt0 + row0) * NH + h) * NVD;
    float* op1 = ao + ((size_t)(bT + qt0 + row1) * NH + h) * NVD;
#pragma unroll
    for (int nt = 0; nt < 8; nt++) {
        int col = half * 64 + nt * 8 + 2 * tg;
        *(float2*)(op0 + col) = make_float2(acc[nt][0] * inv0, acc[nt][1] * inv0);
        *(float2*)(op1 + col) = make_float2(acc[nt][2] * inv1, acc[nt][3] * inv1);
    }
}

// ---------------- launch ----------------
extern "C" void kernel_launch(void* const* d_in, const int* in_sizes, int n_in,
                              void* d_out, int out_size)
{
    const float* x    = (const float*)d_in[0];
    const float* fc   = (const float*)d_in[1];
    const float* fs   = (const float*)d_in[2];
    const float* qdw  = (const float*)d_in[3];
    const float* qnw  = (const float*)d_in[4];
    const float* qunw = (const float*)d_in[5];
    const float* qurw = (const float*)d_in[6];
    const float* kdw  = (const float*)d_in[7];
    const float* kvnw = (const float*)d_in[8];
    const float* kuw  = (const float*)d_in[9];
    const float* qhw  = (const float*)d_in[10];
    const float* khw  = (const float*)d_in[11];
    const float* wow  = (const float*)d_in[12];
    float* out = (float*)d_out;

    float *p_cq, *p_qn, *p_qr, *p_q, *p_kvraw, *p_ckv, *p_kr, *p_kv, *p_k, *p_ao, *p_kdwp;
    cudaGetSymbolAddress((void**)&p_cq,    g_cq);
    cudaGetSymbolAddress((void**)&p_qn,    g_qn);
    cudaGetSymbolAddress((void**)&p_qr,    g_qr);
    cudaGetSymbolAddress((void**)&p_q,     g_q);
    cudaGetSymbolAddress((void**)&p_kvraw, g_kvraw);
    cudaGetSymbolAddress((void**)&p_ckv,   g_ckv);
    cudaGetSymbolAddress((void**)&p_kr,    g_kr);
    cudaGetSymbolAddress((void**)&p_kv,    g_kv);
    cudaGetSymbolAddress((void**)&p_k,     g_k);
    cudaGetSymbolAddress((void**)&p_ao,    g_ao);
    cudaGetSymbolAddress((void**)&p_kdwp,  g_kdwpad);

    cudaFuncSetAttribute(gemm_tf32, cudaFuncAttributeMaxDynamicSharedMemorySize,
                         GEMM_SMEM_BYTES);
    cudaFuncSetAttribute(attn_kernel, cudaFuncAttributeMaxDynamicSharedMemorySize,
                         ATTN_SMEM_BYTES);

    pad_kdw<<<(NDIM * KVP) / 256, 256>>>(kdw, p_kdwp);

    // c_q = x @ q_down_w ; rmsnorm
    gemm_tf32<<<dim3(NQLR / 128, NTOK / 128), 256, GEMM_SMEM_BYTES>>>(x, qdw, p_cq, NTOK, NQLR, NDIM);
    rmsnorm_rows<<<NTOK, 256>>>(p_cq, qnw, NQLR);

    // q projections
    gemm_tf32<<<dim3((NH * NND) / 128, NTOK / 128), 256, GEMM_SMEM_BYTES>>>(p_cq, qunw, p_qn, NTOK, NH * NND, NQLR);
    gemm_tf32<<<dim3((NH * NRD) / 128, NTOK / 128), 256, GEMM_SMEM_BYTES>>>(p_cq, qurw, p_qr, NTOK, NH * NRD, NQLR);

    // kv down (padded to N=640, tf32)
    gemm_tf32<<<dim3(KVP / 128, NTOK / 128), 256, GEMM_SMEM_BYTES>>>(x, p_kdwp, p_kvraw, NTOK, KVP, NDIM);

    // epilogues
    q_build<<<dim3(NH, NTOK), 128>>>(p_qn, p_qr, qhw, fc, fs, p_q);
    kv_post<<<NTOK, 128>>>(p_kvraw, kvnw, fc, fs, p_ckv, p_kr);

    // kv up + k build
    gemm_tf32<<<dim3((NH * (NND + NVD)) / 128, NTOK / 128), 256, GEMM_SMEM_BYTES>>>(p_ckv, kuw, p_kv, NTOK, NH * (NND + NVD), NKVLR);
    k_build<<<dim3(NH, NTOK), 128>>>(p_kv, khw, p_kr, p_k);

    // attention
    attn_kernel<<<dim3(TSEQ / 64, NB * NH), 256, ATTN_SMEM_BYTES>>>(p_q, p_k, p_kv, p_ao);

    // output projection
    gemm_tf32<<<dim3(NDIM / 128, NTOK / 128), 256, GEMM_SMEM_BYTES>>>(p_ao, wow, out, NTOK, NDIM, NH * NVD);
}

// round 16
// speedup vs baseline: 1.5194x; 1.5194x over previous
#include <cuda_runtime.h>
#include <math.h>
#include <stdint.h>

// ---------------- problem constants ----------------
#define NB      2
#define TSEQ    2048
#define NDIM    2048
#define NH      16
#define NQLR    1536
#define NKVLR   512
#define NRD     64
#define NND     128
#define NVD     128
#define NTOK    (NB * TSEQ)        // 4096
#define DQK     (NND + NRD)        // 192
#define KVP     640                 // padded kv_down output width (576 -> 640)
#define EPSV    1e-6f

// ---------------- scratch (no allocations allowed) ----------------
__device__ float g_cq     [(size_t)NTOK * NQLR];
__device__ float g_qn     [(size_t)NTOK * NH * NND];
__device__ float g_qr     [(size_t)NTOK * NH * NRD];
__device__ float g_q      [(size_t)NTOK * NH * DQK];
__device__ float g_kvraw  [(size_t)NTOK * KVP];
__device__ float g_ckv    [(size_t)NTOK * NKVLR];
__device__ float g_kr     [(size_t)NTOK * NRD];
__device__ float g_kv     [(size_t)NTOK * NH * (NND + NVD)];
__device__ float g_k      [(size_t)NTOK * NH * DQK];
__device__ float g_ao     [(size_t)NTOK * NH * NVD];
__device__ float g_kdwpad [(size_t)NDIM * KVP];

// ---------------- helpers ----------------
__device__ __forceinline__ float warp_sum(float v) {
#pragma unroll
    for (int o = 16; o; o >>= 1) v += __shfl_xor_sync(0xffffffffu, v, o);
    return v;
}

__device__ __forceinline__ uint32_t f2tf32(float f) {
    uint32_t r;
    asm("cvt.rna.tf32.f32 %0, %1;" : "=r"(r) : "f"(f));
    return r;
}

__device__ __forceinline__ void mma_tf32(
    float& c0, float& c1, float& c2, float& c3,
    uint32_t a0, uint32_t a1, uint32_t a2, uint32_t a3,
    uint32_t b0, uint32_t b1)
{
    asm volatile(
        "mma.sync.aligned.m16n8k8.row.col.f32.tf32.tf32.f32 "
        "{%0,%1,%2,%3}, {%4,%5,%6,%7}, {%8,%9}, {%0,%1,%2,%3};"
        : "+f"(c0), "+f"(c1), "+f"(c2), "+f"(c3)
        : "r"(a0), "r"(a1), "r"(a2), "r"(a3), "r"(b0), "r"(b1));
}

__device__ __forceinline__ void cp16(uint32_t dst_smem, const void* src) {
    asm volatile("cp.async.cg.shared.global [%0], [%1], 16;\n"
                 :: "r"(dst_smem), "l"(src) : "memory");
}
#define CP_COMMIT() asm volatile("cp.async.commit_group;\n" ::: "memory")
#define CP_WAIT(N)  asm volatile("cp.async.wait_group %0;\n" :: "n"(N) : "memory")

// ============ tf32 tensor-core GEMM (R13 structure + fragment double-buffer) ============
// 128x128x32 block tile, 8 warps, 64x32 warp tile. Register-staged global->smem
// double buffer; tf32 cvt at staging. Fragment ping-pong overlaps LDS with MMA.
// C[M,N] = A[M,K] @ B[K,N], row-major. M%128==0, N%128==0, K%32==0.
#define AS_WORDS 4608            // 128*36
#define BS_WORDS 4352            // 32*136
#define STAGE_WORDS (AS_WORDS + BS_WORDS)
#define GEMM_SMEM_BYTES (2 * STAGE_WORDS * 4)   // 71680

__global__ __launch_bounds__(256, 1) void gemm_tf32(
    const float* __restrict__ A, const float* __restrict__ B,
    float* __restrict__ C, int M, int N, int K)
{
    extern __shared__ uint32_t gsm[];

    const int tid  = threadIdx.x;
    const int wid  = tid >> 5;
    const int lane = tid & 31;
    const int g    = lane >> 2;
    const int tg   = lane & 3;
    const int warp_m = (wid >> 2) * 64;
    const int warp_n = (wid & 3) * 32;

    const int m0 = blockIdx.y << 7;
    const int n0 = blockIdx.x << 7;

    const int ar  = tid >> 3;
    const int akq = (tid & 7) << 2;
    const int br  = tid >> 5;
    const int bc  = (tid & 31) << 2;

    float acc[4][4][4];
#pragma unroll
    for (int mt = 0; mt < 4; mt++)
#pragma unroll
        for (int nt = 0; nt < 4; nt++)
#pragma unroll
            for (int c = 0; c < 4; c++) acc[mt][nt][c] = 0.f;

    const int nk = K >> 5;
    float4 av[4], bv[4];

    // prologue: load tile 0 and stage into buffer 0
#pragma unroll
    for (int p = 0; p < 4; p++) {
        av[p] = *(const float4*)(A + (size_t)(m0 + ar + p * 32) * K + akq);
        bv[p] = *(const float4*)(B + (size_t)(br + p * 8) * N + n0 + bc);
    }
    {
        uint32_t* As = gsm;
        uint32_t* Bs = gsm + AS_WORDS;
#pragma unroll
        for (int p = 0; p < 4; p++) {
            uint32_t* da = &As[(ar + p * 32) * 36 + akq];
            da[0] = f2tf32(av[p].x); da[1] = f2tf32(av[p].y);
            da[2] = f2tf32(av[p].z); da[3] = f2tf32(av[p].w);
            uint32_t* db = &Bs[(br + p * 8) * 136 + bc];
            db[0] = f2tf32(bv[p].x); db[1] = f2tf32(bv[p].y);
            db[2] = f2tf32(bv[p].z); db[3] = f2tf32(bv[p].w);
        }
    }

    for (int it = 0; it < nk; it++) {
        uint32_t* As = gsm + (it & 1) * STAGE_WORDS;
        uint32_t* Bs = As + AS_WORDS;
        __syncthreads();

        const bool more = (it + 1 < nk);
        if (more) {
            const int k0 = (it + 1) << 5;
#pragma unroll
            for (int p = 0; p < 4; p++) {
                av[p] = *(const float4*)(A + (size_t)(m0 + ar + p * 32) * K + k0 + akq);
                bv[p] = *(const float4*)(B + (size_t)(k0 + br + p * 8) * N + n0 + bc);
            }
        }

        // ---- fragment ping-pong over 4 k8-steps ----
        uint32_t afr[2][4][4], bfr[2][4][2];
        // preload k8 = 0 into buffer 0
#pragma unroll
        for (int mt = 0; mt < 4; mt++) {
            const int m = warp_m + mt * 16;
            afr[0][mt][0] = As[(m + g) * 36 + tg];
            afr[0][mt][1] = As[(m + g + 8) * 36 + tg];
            afr[0][mt][2] = As[(m + g) * 36 + tg + 4];
            afr[0][mt][3] = As[(m + g + 8) * 36 + tg + 4];
        }
#pragma unroll
        for (int nt = 0; nt < 4; nt++) {
            const int n = warp_n + nt * 8;
            bfr[0][nt][0] = Bs[tg * 136 + n + g];
            bfr[0][nt][1] = Bs[(tg + 4) * 136 + n + g];
        }

#pragma unroll
        for (int k8 = 0; k8 < 4; k8++) {
            const int cur = k8 & 1;
            const int nxt = cur ^ 1;
            if (k8 < 3) {
                const int kk = (k8 + 1) * 8;
#pragma unroll
                for (int mt = 0; mt < 4; mt++) {
                    const int m = warp_m + mt * 16;
                    afr[nxt][mt][0] = As[(m + g) * 36 + kk + tg];
                    afr[nxt][mt][1] = As[(m + g + 8) * 36 + kk + tg];
                    afr[nxt][mt][2] = As[(m + g) * 36 + kk + tg + 4];
                    afr[nxt][mt][3] = As[(m + g + 8) * 36 + kk + tg + 4];
                }
#pragma unroll
                for (int nt = 0; nt < 4; nt++) {
                    const int n = warp_n + nt * 8;
                    bfr[nxt][nt][0] = Bs[(kk + tg) * 136 + n + g];
                    bfr[nxt][nt][1] = Bs[(kk + tg + 4) * 136 + n + g];
                }
            }
#pragma unroll
            for (int mt = 0; mt < 4; mt++)
#pragma unroll
                for (int nt = 0; nt < 4; nt++)
                    mma_tf32(acc[mt][nt][0], acc[mt][nt][1], acc[mt][nt][2], acc[mt][nt][3],
                             afr[cur][mt][0], afr[cur][mt][1], afr[cur][mt][2], afr[cur][mt][3],
                             bfr[cur][nt][0], bfr[cur][nt][1]);
        }

        if (more) {
            uint32_t* Asn = gsm + ((it + 1) & 1) * STAGE_WORDS;
            uint32_t* Bsn = Asn + AS_WORDS;
#pragma unroll
            for (int p = 0; p < 4; p++) {
                uint32_t* da = &Asn[(ar + p * 32) * 36 + akq];
                da[0] = f2tf32(av[p].x); da[1] = f2tf32(av[p].y);
                da[2] = f2tf32(av[p].z); da[3] = f2tf32(av[p].w);
                uint32_t* db = &Bsn[(br + p * 8) * 136 + bc];
                db[0] = f2tf32(bv[p].x); db[1] = f2tf32(bv[p].y);
                db[2] = f2tf32(bv[p].z); db[3] = f2tf32(bv[p].w);
            }
        }
    }

#pragma unroll
    for (int mt = 0; mt < 4; mt++) {
        const int row = m0 + warp_m + mt * 16 + g;
#pragma unroll
        for (int nt = 0; nt < 4; nt++) {
            const int col = n0 + warp_n + nt * 8 + tg * 2;
            *(float2*)(C + (size_t)row * N + col)       = make_float2(acc[mt][nt][0], acc[mt][nt][1]);
            *(float2*)(C + (size_t)(row + 8) * N + col) = make_float2(acc[mt][nt][2], acc[mt][nt][3]);
        }
    }
}

// ---------------- pad kv_down_w (2048x576) into (2048x640), zero-filled ----------------
__global__ __launch_bounds__(256) void pad_kdw(
    const float* __restrict__ w, float* __restrict__ o)
{
    int idx = blockIdx.x * 256 + threadIdx.x;
    int r = idx / KVP, c = idx - r * KVP;
    o[idx] = (c < NKVLR + NRD) ? w[r * (NKVLR + NRD) + c] : 0.f;
}

// ---------------- row-wise rmsnorm (in place), 256 threads ----------------
__global__ __launch_bounds__(256) void rmsnorm_rows(
    float* __restrict__ x, const float* __restrict__ w, int len)
{
    __shared__ float sb[8];
    float* row = x + (size_t)blockIdx.x * len;
    float ss = 0.f;
    for (int i = threadIdx.x; i < len; i += 256) { float v = row[i]; ss += v * v; }
    ss = warp_sum(ss);
    if ((threadIdx.x & 31) == 0) sb[threadIdx.x >> 5] = ss;
    __syncthreads();
    float tot = 0.f;
#pragma unroll
    for (int i = 0; i < 8; i++) tot += sb[i];
    float sc = rsqrtf(tot / (float)len + EPSV);
    for (int i = threadIdx.x; i < len; i += 256) row[i] = row[i] * sc * w[i];
}

// ---------------- build q ----------------
__global__ __launch_bounds__(128) void q_build(
    const float* __restrict__ qn, const float* __restrict__ qr,
    const float* __restrict__ qhw,
    const float* __restrict__ fc, const float* __restrict__ fs,
    float* __restrict__ q)
{
    __shared__ float sb[4];
    const int token = blockIdx.y, h = blockIdx.x;
    const int t = token & (TSEQ - 1);
    const float* xn = qn + (size_t)token * NH * NND + h * NND;
    float v = xn[threadIdx.x];
    float ss = warp_sum(v * v);
    if ((threadIdx.x & 31) == 0) sb[threadIdx.x >> 5] = ss;
    __syncthreads();
    float tot = sb[0] + sb[1] + sb[2] + sb[3];
    float sc = rsqrtf(tot / (float)NND + EPSV);
    float* qo = q + ((size_t)token * NH + h) * DQK;
    qo[threadIdx.x] = v * sc * qhw[threadIdx.x];
    if (threadIdx.x < NRD / 2) {
        int i = threadIdx.x;
        const float* xr = qr + (size_t)token * NH * NRD + h * NRD;
        float a = xr[2 * i], b = xr[2 * i + 1];
        float c = fc[t * (NRD / 2) + i], s = fs[t * (NRD / 2) + i];
        qo[NND + 2 * i]     = a * c - b * s;
        qo[NND + 2 * i + 1] = a * s + b * c;
    }
}

// ---------------- kv post (reads padded kvraw, stride KVP) ----------------
__global__ __launch_bounds__(128) void kv_post(
    const float* __restrict__ kvraw, const float* __restrict__ kvw,
    const float* __restrict__ fc, const float* __restrict__ fs,
    float* __restrict__ ckv, float* __restrict__ kr)
{
    __shared__ float sb[4];
    const int token = blockIdx.x;
    const int t = token & (TSEQ - 1);
    const float* row = kvraw + (size_t)token * KVP;
    float ss = 0.f;
    for (int i = threadIdx.x; i < NKVLR; i += 128) { float v = row[i]; ss += v * v; }
    ss = warp_sum(ss);
    if ((threadIdx.x & 31) == 0) sb[threadIdx.x >> 5] = ss;
    __syncthreads();
    float tot = sb[0] + sb[1] + sb[2] + sb[3];
    float sc = rsqrtf(tot / (float)NKVLR + EPSV);
    for (int i = threadIdx.x; i < NKVLR; i += 128)
        ckv[(size_t)token * NKVLR + i] = row[i] * sc * kvw[i];
    if (threadIdx.x < NRD / 2) {
        int i = threadIdx.x;
        float a = row[NKVLR + 2 * i], b = row[NKVLR + 2 * i + 1];
        float c = fc[t * (NRD / 2) + i], s = fs[t * (NRD / 2) + i];
        kr[(size_t)token * NRD + 2 * i]     = a * c - b * s;
        kr[(size_t)token * NRD + 2 * i + 1] = a * s + b * c;
    }
}

// ---------------- build k ----------------
__global__ __launch_bounds__(128) void k_build(
    const float* __restrict__ kv, const float* __restrict__ khw,
    const float* __restrict__ kr, float* __restrict__ k)
{
    __shared__ float sb[4];
    const int token = blockIdx.y, h = blockIdx.x;
    const float* kn = kv + ((size_t)token * NH + h) * (NND + NVD);
    float v = kn[threadIdx.x];
    float ss = warp_sum(v * v);
    if ((threadIdx.x & 31) == 0) sb[threadIdx.x >> 5] = ss;
    __syncthreads();
    float tot = sb[0] + sb[1] + sb[2] + sb[3];
    float sc = rsqrtf(tot / (float)NND + EPSV);
    float* ko = k + ((size_t)token * NH + h) * DQK;
    ko[threadIdx.x] = v * sc * khw[threadIdx.x];
    if (threadIdx.x < NRD) ko[NND + threadIdx.x] = kr[(size_t)token * NRD + threadIdx.x];
}

// ============ causal flash attention v5: tf32 MMA for QK^T and PV ============
#define QS_OFF 0
#define KS_OFF 12544
#define KS_SZ  12544
#define VS_OFF 37632
#define PS_OFF 46336
#define MX_OFF 50688
#define SX_OFF 50816
#define ATTN_SMEM_BYTES (50944 * 4)   // 203776

__global__ __launch_bounds__(256) void attn_kernel(
    const float* __restrict__ q, const float* __restrict__ k,
    const float* __restrict__ kv, float* __restrict__ ao)
{
    extern __shared__ float sm[];
    float* Qs = sm + QS_OFF;
    float* Vs = sm + VS_OFF;
    float* Ps = sm + PS_OFF;
    float* Mx = sm + MX_OFF;
    float* Sx = sm + SX_OFF;
    const uint32_t smb = (uint32_t)__cvta_generic_to_shared(sm);

    const int tid  = threadIdx.x;
    const int wid  = tid >> 5;
    const int lane = tid & 31;
    const int g    = lane >> 2;
    const int tg   = lane & 3;
    const int warp_m = (wid >> 1) * 16;
    const int half   = wid & 1;
    const int row0 = warp_m + g;
    const int row1 = row0 + 8;

    const int qt = (int)gridDim.x - 1 - (int)blockIdx.x;
    const int bh = blockIdx.y;
    const int b = bh >> 4, h = bh & 15;
    const int qt0 = qt << 6;
    const int bT = b * TSEQ;
    const float SCALE = 0.07216878364870322f;

    const float* qh = q  + ((size_t)(bT + qt0) * NH + h) * DQK;
    const float* vh = kv + ((size_t)bT * NH + h) * (NND + NVD) + NND;

    const int lrow = tid >> 2;
    const int lq0  = (tid & 3) * 12;

#pragma unroll
    for (int p = 0; p < 12; p++) {
        int quad = lq0 + p;
        cp16(smb + (QS_OFF + lrow * 196 + quad * 4) * 4,
             qh + (size_t)lrow * (NH * DQK) + quad * 4);
    }
    {
        const float* kh0 = k + ((size_t)bT * NH + h) * DQK;
#pragma unroll
        for (int p = 0; p < 12; p++) {
            int quad = lq0 + p;
            cp16(smb + (KS_OFF + lrow * 196 + quad * 4) * 4,
                 kh0 + (size_t)lrow * (NH * DQK) + quad * 4);
        }
    }
    CP_COMMIT();
#pragma unroll
    for (int p = 0; p < 8; p++) {
        int c = p * 256 + tid;
        int j = c >> 5, off = (c & 31) * 4;
        cp16(smb + (VS_OFF + j * 136 + off) * 4,
             vh + (size_t)j * (NH * (NND + NVD)) + off);
    }
    CP_COMMIT();

    float rm0 = -1e30f, rm1 = -1e30f, rl0 = 0.f, rl1 = 0.f;
    float acc[8][4];
#pragma unroll
    for (int nt = 0; nt < 8; nt++)
#pragma unroll
        for (int c = 0; c < 4; c++) acc[nt][c] = 0.f;

    for (int kt = 0; kt <= qt; kt++) {
        CP_WAIT(1);
        __syncthreads();

        if (kt == 0) {
            for (int i = tid; i < 12544; i += 256)
                Qs[i] = __uint_as_float(f2tf32(Qs[i]));
            __syncthreads();
        }

        if (kt < qt) {
            const float* khn = k + ((size_t)(bT + (kt + 1) * 64) * NH + h) * DQK;
            const uint32_t kdst = smb + (KS_OFF + ((kt + 1) & 1) * KS_SZ) * 4;
#pragma unroll
            for (int p = 0; p < 12; p++) {
                int quad = lq0 + p;
                cp16(kdst + (lrow * 196 + quad * 4) * 4,
                     khn + (size_t)lrow * (NH * DQK) + quad * 4);
            }
            CP_COMMIT();
        }

        const float* Ks = sm + KS_OFF + (kt & 1) * KS_SZ;
        const int warp_n = half * 32;

        float s[4][4];
#pragma unroll
        for (int nt = 0; nt < 4; nt++)
#pragma unroll
            for (int c = 0; c < 4; c++) s[nt][c] = 0.f;

#pragma unroll 4
        for (int ks = 0; ks < 24; ks++) {
            const int kk = ks * 8;
            uint32_t a0 = __float_as_uint(Qs[row0 * 196 + kk + tg]);
            uint32_t a1 = __float_as_uint(Qs[row1 * 196 + kk + tg]);
            uint32_t a2 = __float_as_uint(Qs[row0 * 196 + kk + tg + 4]);
            uint32_t a3 = __float_as_uint(Qs[row1 * 196 + kk + tg + 4]);
#pragma unroll
            for (int nt = 0; nt < 4; nt++) {
                const int n = warp_n + nt * 8 + g;
                uint32_t b0 = f2tf32(Ks[n * 196 + kk + tg]);
                uint32_t b1 = f2tf32(Ks[n * 196 + kk + tg + 4]);
                mma_tf32(s[nt][0], s[nt][1], s[nt][2], s[nt][3],
                         a0, a1, a2, a3, b0, b1);
            }
        }

#pragma unroll
        for (int nt = 0; nt < 4; nt++)
#pragma unroll
            for (int c = 0; c < 4; c++) s[nt][c] *= SCALE;
        if (kt == qt) {
#pragma unroll
            for (int nt = 0; nt < 4; nt++) {
                int col = warp_n + nt * 8 + 2 * tg;
                if (col     > row0) s[nt][0] = -1e30f;
                if (col + 1 > row0) s[nt][1] = -1e30f;
                if (col     > row1) s[nt][2] = -1e30f;
                if (col + 1 > row1) s[nt][3] = -1e30f;
            }
        }

        float m0p = -1e30f, m1p = -1e30f;
#pragma unroll
        for (int nt = 0; nt < 4; nt++) {
            m0p = fmaxf(m0p, fmaxf(s[nt][0], s[nt][1]));
            m1p = fmaxf(m1p, fmaxf(s[nt][2], s[nt][3]));
        }
        m0p = fmaxf(m0p, __shfl_xor_sync(0xffffffffu, m0p, 1));
        m0p = fmaxf(m0p, __shfl_xor_sync(0xffffffffu, m0p, 2));
        m1p = fmaxf(m1p, __shfl_xor_sync(0xffffffffu, m1p, 1));
        m1p = fmaxf(m1p, __shfl_xor_sync(0xffffffffu, m1p, 2));
        if (tg == 0) {
            Mx[half * 64 + row0] = m0p;
            Mx[half * 64 + row1] = m1p;
        }
        __syncthreads();

        float mn0 = fmaxf(rm0, fmaxf(Mx[row0], Mx[64 + row0]));
        float mn1 = fmaxf(rm1, fmaxf(Mx[row1], Mx[64 + row1]));
        float corr0 = __expf(rm0 - mn0);
        float corr1 = __expf(rm1 - mn1);
        rm0 = mn0; rm1 = mn1;

        float s0p = 0.f, s1p = 0.f;
#pragma unroll
        for (int nt = 0; nt < 4; nt++) {
            float e0 = __expf(s[nt][0] - mn0);
            float e1 = __expf(s[nt][1] - mn0);
            float e2 = __expf(s[nt][2] - mn1);
            float e3 = __expf(s[nt][3] - mn1);
            s0p += e0 + e1;
            s1p += e2 + e3;
            int col = warp_n + nt * 8 + 2 * tg;
            *(float2*)&Ps[row0 * 68 + col] =
                make_float2(__uint_as_float(f2tf32(e0)), __uint_as_float(f2tf32(e1)));
            *(float2*)&Ps[row1 * 68 + col] =
                make_float2(__uint_as_float(f2tf32(e2)), __uint_as_float(f2tf32(e3)));
        }
        s0p += __shfl_xor_sync(0xffffffffu, s0p, 1);
        s0p += __shfl_xor_sync(0xffffffffu, s0p, 2);
        s1p += __shfl_xor_sync(0xffffffffu, s1p, 1);
        s1p += __shfl_xor_sync(0xffffffffu, s1p, 2);
        if (tg == 0) {
            Sx[half * 64 + row0] = s0p;
            Sx[half * 64 + row1] = s1p;
        }

#pragma unroll
        for (int nt = 0; nt < 8; nt++) {
            acc[nt][0] *= corr0; acc[nt][1] *= corr0;
            acc[nt][2] *= corr1; acc[nt][3] *= corr1;
        }

        if (kt < qt) { CP_WAIT(1); } else { CP_WAIT(0); }
        __syncthreads();

        rl0 = rl0 * corr0 + Sx[row0] + Sx[64 + row0];
        rl1 = rl1 * corr1 + Sx[row1] + Sx[64 + row1];

#pragma unroll
        for (int ks = 0; ks < 8; ks++) {
            const int kk = ks * 8;
            uint32_t a0 = __float_as_uint(Ps[row0 * 68 + kk + tg]);
            uint32_t a1 = __float_as_uint(Ps[row1 * 68 + kk + tg]);
            uint32_t a2 = __float_as_uint(Ps[row0 * 68 + kk + tg + 4]);
            uint32_t a3 = __float_as_uint(Ps[row1 * 68 + kk + tg + 4]);
#pragma unroll
            for (int nt = 0; nt < 8; nt++) {
                const int n = half * 64 + nt * 8 + g;
                uint32_t b0 = f2tf32(Vs[(kk + tg) * 136 + n]);
                uint32_t b1 = f2tf32(Vs[(kk + tg + 4) * 136 + n]);
                mma_tf32(acc[nt][0], acc[nt][1], acc[nt][2], acc[nt][3],
                         a0, a1, a2, a3, b0, b1);
            }
        }
        __syncthreads();

        if (kt < qt) {
            const float* vhn = vh + (size_t)(kt + 1) * 64 * (NH * (NND + NVD));
#pragma unroll
            for (int p = 0; p < 8; p++) {
                int c = p * 256 + tid;
                int j = c >> 5, off = (c & 31) * 4;
                cp16(smb + (VS_OFF + j * 136 + off) * 4,
                     vhn + (size_t)j * (NH * (NND + NVD)) + off);
            }
            CP_COMMIT();
        }
    }

    const float inv0 = 1.f / rl0;
    const float inv1 = 1.f / rl1;
    float* op0 = ao + ((size_t)(bT + qt0 + row0) * NH + h) * NVD;
    float* op1 = ao + ((size_t)(bT + qt0 + row1) * NH + h) * NVD;
#pragma unroll
    for (int nt = 0; nt < 8; nt++) {
        int col = half * 64 + nt * 8 + 2 * tg;
        *(float2*)(op0 + col) = make_float2(acc[nt][0] * inv0, acc[nt][1] * inv0);
        *(float2*)(op1 + col) = make_float2(acc[nt][2] * inv1, acc[nt][3] * inv1);
    }
}

// ---------------- launch ----------------
extern "C" void kernel_launch(void* const* d_in, const int* in_sizes, int n_in,
                              void* d_out, int out_size)
{
    const float* x    = (const float*)d_in[0];
    const float* fc   = (const float*)d_in[1];
    const float* fs   = (const float*)d_in[2];
    const float* qdw  = (const float*)d_in[3];
    const float* qnw  = (const float*)d_in[4];
    const float* qunw = (const float*)d_in[5];
    const float* qurw = (const float*)d_in[6];
    const float* kdw  = (const float*)d_in[7];
    const float* kvnw = (const float*)d_in[8];
    const float* kuw  = (const float*)d_in[9];
    const float* qhw  = (const float*)d_in[10];
    const float* khw  = (const float*)d_in[11];
    const float* wow  = (const float*)d_in[12];
    float* out = (float*)d_out;

    float *p_cq, *p_qn, *p_qr, *p_q, *p_kvraw, *p_ckv, *p_kr, *p_kv, *p_k, *p_ao, *p_kdwp;
    cudaGetSymbolAddress((void**)&p_cq,    g_cq);
    cudaGetSymbolAddress((void**)&p_qn,    g_qn);
    cudaGetSymbolAddress((void**)&p_qr,    g_qr);
    cudaGetSymbolAddress((void**)&p_q,     g_q);
    cudaGetSymbolAddress((void**)&p_kvraw, g_kvraw);
    cudaGetSymbolAddress((void**)&p_ckv,   g_ckv);
    cudaGetSymbolAddress((void**)&p_kr,    g_kr);
    cudaGetSymbolAddress((void**)&p_kv,    g_kv);
    cudaGetSymbolAddress((void**)&p_k,     g_k);
    cudaGetSymbolAddress((void**)&p_ao,    g_ao);
    cudaGetSymbolAddress((void**)&p_kdwp,  g_kdwpad);

    cudaFuncSetAttribute(gemm_tf32, cudaFuncAttributeMaxDynamicSharedMemorySize,
                         GEMM_SMEM_BYTES);
    cudaFuncSetAttribute(attn_kernel, cudaFuncAttributeMaxDynamicSharedMemorySize,
                         ATTN_SMEM_BYTES);

    pad_kdw<<<(NDIM * KVP) / 256, 256>>>(kdw, p_kdwp);

    // c_q = x @ q_down_w ; rmsnorm
    gemm_tf32<<<dim3(NQLR / 128, NTOK / 128), 256, GEMM_SMEM_BYTES>>>(x, qdw, p_cq, NTOK, NQLR, NDIM);
    rmsnorm_rows<<<NTOK, 256>>>(p_cq, qnw, NQLR);

    // q projections
    gemm_tf32<<<dim3((NH * NND) / 128, NTOK / 128), 256, GEMM_SMEM_BYTES>>>(p_cq, qunw, p_qn, NTOK, NH * NND, NQLR);
    gemm_tf32<<<dim3((NH * NRD) / 128, NTOK / 128), 256, GEMM_SMEM_BYTES>>>(p_cq, qurw, p_qr, NTOK, NH * NRD, NQLR);

    // kv down (padded to N=640, tf32)
    gemm_tf32<<<dim3(KVP / 128, NTOK / 128), 256, GEMM_SMEM_BYTES>>>(x, p_kdwp, p_kvraw, NTOK, KVP, NDIM);

    // epilogues
    q_build<<<dim3(NH, NTOK), 128>>>(p_qn, p_qr, qhw, fc, fs, p_q);
    kv_post<<<NTOK, 128>>>(p_kvraw, kvnw, fc, fs, p_ckv, p_kr);

    // kv up + k build
    gemm_tf32<<<dim3((NH * (NND + NVD)) / 128, NTOK / 128), 256, GEMM_SMEM_BYTES>>>(p_ckv, kuw, p_kv, NTOK, NH * (NND + NVD), NKVLR);
    k_build<<<dim3(NH, NTOK), 128>>>(p_kv, khw, p_kr, p_k);

    // attention
    attn_kernel<<<dim3(TSEQ / 64, NB * NH), 256, ATTN_SMEM_BYTES>>>(p_q, p_k, p_kv, p_ao);

    // output projection
    gemm_tf32<<<dim3(NDIM / 128, NTOK / 128), 256, GEMM_SMEM_BYTES>>>(p_ao, wow, out, NTOK, NDIM, NH * NVD);
}